// round 3
// baseline (speedup 1.0000x reference)
#include <cuda_runtime.h>
#include <cuda_fp16.h>

#define GR 16
#define NCELL 256
typedef unsigned long long ull;

// fp16 grid table: per cell 12 half2 words:
//  [0..2] A0 (gamma*ln_w - 1, layer0, ch pairs 01/23/45), [3..5] B0, [6..8] A1, [9..11] B1
__device__ unsigned g_gridh[NCELL * 12];
__constant__ float c_wts[81];   // w_in@0(12) b_in@12(6) w_h@18(36) b_h@54(6) w_out@60(18) b_out@78(3)

__global__ void prep_kernel(const float* __restrict__ gamma, const float* __restrict__ beta,
                            const float* __restrict__ lnw, const float* __restrict__ lnb) {
    int idx = blockIdx.x * blockDim.x + threadIdx.x;
    if (idx >= NCELL * 12) return;
    int cell = idx / 12, j = idx - cell * 12;
    int l = j / 6, jj = j - l * 6;
    int isB = jj / 3, pr = jj - isB * 3;
    float v[2];
#pragma unroll
    for (int u = 0; u < 2; u++) {
        int c = 2 * pr + u;
        float g = gamma[(l * 6 + c) * NCELL + cell];
        if (isB) v[u] = beta[(l * 6 + c) * NCELL + cell] + g * lnb[l * 6 + c];
        else     v[u] = g * lnw[l * 6 + c] - 1.0f;
    }
    __half2 h = __floats2half2_rn(v[0], v[1]);
    g_gridh[cell * 12 + j] = *reinterpret_cast<unsigned*>(&h);
}

// ---------------- packed f32x2 helpers ----------------
__device__ __forceinline__ ull pk2(float a, float b) {
    ull r; asm("mov.b64 %0, {%1,%2};" : "=l"(r) : "f"(a), "f"(b)); return r;
}
__device__ __forceinline__ float2 upk(ull r) {
    float2 o; asm("mov.b64 {%0,%1}, %2;" : "=f"(o.x), "=f"(o.y) : "l"(r)); return o;
}
#define C2(v) pk2((v), (v))
#define FMA2(d, a, b, c) asm("fma.rn.f32x2 %0,%1,%2,%3;" : "=l"(d) : "l"(a), "l"(b), "l"(c))
#define MUL2(d, a, b)    asm("mul.rn.f32x2 %0,%1,%2;"    : "=l"(d) : "l"(a), "l"(b))
#define ADD2(d, a, b)    asm("add.rn.f32x2 %0,%1,%2;"    : "=l"(d) : "l"(a), "l"(b))

// Packed silu, zero MUFU: t = 2^(-|x|*log2e) via magic-round + deg-5 poly,
// s = t/(1+t) via seeded Newton rcp (d in [1,2]), reflect for x>0.
__device__ __forceinline__ ull silu2p(ull x) {
    float2 xv = upk(x);
    ull nax = x | 0x8000000080000000ull;      // -|x|
    ull y;  MUL2(y, nax, C2(1.4426950408889634f));
    ull fm; ADD2(fm, y, C2(12582912.0f));
    float2 fmv = upk(fm);
    int n0 = __float_as_int(fmv.x) << 23;
    int n1 = __float_as_int(fmv.y) << 23;
    ull fms; ADD2(fms, fm, C2(-12582912.0f)); // round(y)
    ull f;   FMA2(f, fms, C2(-1.0f), y);      // frac in [-0.5, 0.5]
    ull p;
    FMA2(p, f, C2(1.3333558e-3f), C2(9.6181291e-3f));
    FMA2(p, f, p, C2(5.5504109e-2f));
    FMA2(p, f, p, C2(2.4022651e-1f));
    FMA2(p, f, p, C2(6.9314718e-1f));
    FMA2(p, f, p, C2(1.0f));
    float2 pv = upk(p);
    ull t = pk2(__int_as_float(__float_as_int(pv.x) + n0),
                __int_as_float(__float_as_int(pv.y) + n1));
    ull d;  ADD2(d, t, C2(1.0f));             // in [1,2]
    ull r;  FMA2(r, d, C2(-8.0f / 17.0f), C2(24.0f / 17.0f));
    ull nd = d ^ 0x8000000080000000ull;
    ull u;
    FMA2(u, nd, r, C2(2.0f)); MUL2(r, r, u);
    FMA2(u, nd, r, C2(2.0f)); MUL2(r, r, u);  // rel err ~1.2e-5
    ull s;  MUL2(s, t, r);                    // sigmoid(-|x|)
    ull m;  MUL2(m, x, s);
    float2 mv = upk(m);
    return pk2(xv.x > 0.0f ? xv.x - mv.x : mv.x,
               xv.y > 0.0f ? xv.y - mv.y : mv.y);
}

__device__ __forceinline__ __half2 hr(unsigned u) { return *reinterpret_cast<__half2*>(&u); }
__device__ __forceinline__ ull h2f2(__half2 v) { float2 f = __half22float2(v); return pk2(f.x, f.y); }

// packed layernorm + FiLM; A delta-coded: h = (1+A)*norm + B
__device__ __forceinline__ void modulate2(ull& h01, ull& h23, ull& h45,
                                          ull A01, ull A23, ull A45,
                                          ull B01, ull B23, ull B45) {
    ull sp; ADD2(sp, h01, h23); ADD2(sp, sp, h45);
    float2 sv = upk(sp);
    float nmu = (sv.x + sv.y) * (-1.0f / 6.0f);
    ull nmu2 = C2(nmu);
    ull c01, c23, c45;
    ADD2(c01, h01, nmu2); ADD2(c23, h23, nmu2); ADD2(c45, h45, nmu2);
    ull q; MUL2(q, c01, c01); FMA2(q, c23, c23, q); FMA2(q, c45, c45, q);
    float2 qv = upk(q);
    float v = fmaf(qv.x + qv.y, 1.0f / 6.0f, 1e-5f);
    float r = __int_as_float(0x5f3759df - (__float_as_int(v) >> 1));
    float hv = 0.5f * v;
    r = r * fmaf(-hv, r * r, 1.5f);
    r = r * fmaf(-hv, r * r, 1.5f);           // rel err ~5e-6
    ull r2 = C2(r);
    ull t01, t23, t45;
    MUL2(t01, c01, r2); MUL2(t23, c23, r2); MUL2(t45, c45, r2);
    ull u01, u23, u45;
    ADD2(u01, t01, B01); ADD2(u23, t23, B23); ADD2(u45, t45, B45);
    FMA2(h01, A01, t01, u01); FMA2(h23, A23, t23, u23); FMA2(h45, A45, t45, u45);
}

#define CMB(dst, Aw, Bw, Cw, Dw) \
    dst = __hfma2(hr(Dw), W11, __hfma2(hr(Cw), W10, __hfma2(hr(Bw), W01, __hmul2(hr(Aw), W00))))

// ---------------- main kernel ----------------
__global__ __launch_bounds__(256, 3)
void camfield_kernel(const float2* __restrict__ xy, float* __restrict__ out, int n) {
    // cell stride 20 words (80B = 5 x 16B chunks, coprime with 8 chunk columns)
    __shared__ __align__(16) unsigned sg[NCELL * 20];
    for (int i = threadIdx.x; i < NCELL * 12; i += blockDim.x)
        sg[(i / 12) * 20 + (i % 12)] = g_gridh[i];
    __syncthreads();

    const int stride = gridDim.x * blockDim.x;
#pragma unroll 1
    for (int i = blockIdx.x * blockDim.x + threadIdx.x; i < n; i += stride) {
        float2 pt = xy[i];

        float fx = fminf(fmaxf(fmaf(pt.x, 7.5f, 7.5f), 0.0f), 15.0f);
        float fy = fminf(fmaxf(fmaf(pt.y, 7.5f, 7.5f), 0.0f), 15.0f);
        float x0f = floorf(fx), y0f = floorf(fy);
        float wx = fx - x0f, wy = fy - y0f;
        int x0 = (int)x0f, y0 = (int)y0f;
        int x1 = min(x0 + 1, GR - 1), y1 = min(y0 + 1, GR - 1);
        const uint4* p00 = (const uint4*)&sg[((y0 << 4) + x0) * 20];
        const uint4* p01 = (const uint4*)&sg[((y0 << 4) + x1) * 20];
        const uint4* p10 = (const uint4*)&sg[((y1 << 4) + x0) * 20];
        const uint4* p11 = (const uint4*)&sg[((y1 << 4) + x1) * 20];

        float w11f = wx * wy;
        __half2 W11 = __float2half2_rn(w11f);
        __half2 W01 = __float2half2_rn(wx - w11f);
        __half2 W10 = __float2half2_rn(wy - w11f);
        __half2 W00 = __float2half2_rn(1.0f - wx - wy + w11f);

        uint4 a0 = p00[0], a1 = p00[1], a2 = p00[2];
        uint4 b0 = p01[0], b1 = p01[1], b2 = p01[2];
        uint4 c0 = p10[0], c1 = p10[1], c2 = p10[2];
        uint4 d0 = p11[0], d1 = p11[1], d2 = p11[2];

        __half2 v0, v1, v2, v3, v4, v5, v6, v7, v8, v9, v10, v11;
        CMB(v0,  a0.x, b0.x, c0.x, d0.x);  CMB(v1,  a0.y, b0.y, c0.y, d0.y);
        CMB(v2,  a0.z, b0.z, c0.z, d0.z);  CMB(v3,  a0.w, b0.w, c0.w, d0.w);
        CMB(v4,  a1.x, b1.x, c1.x, d1.x);  CMB(v5,  a1.y, b1.y, c1.y, d1.y);
        CMB(v6,  a1.z, b1.z, c1.z, d1.z);  CMB(v7,  a1.w, b1.w, c1.w, d1.w);
        CMB(v8,  a2.x, b2.x, c2.x, d2.x);  CMB(v9,  a2.y, b2.y, c2.y, d2.y);
        CMB(v10, a2.z, b2.z, c2.z, d2.z);  CMB(v11, a2.w, b2.w, c2.w, d2.w);

        // input layer: silu(xy @ w_in^T + b_in), packed pairs
        ull h01, h23, h45;
        {
            float pre[6];
#pragma unroll
            for (int c = 0; c < 6; c++)
                pre[c] = fmaf(c_wts[2 * c], pt.x, fmaf(c_wts[2 * c + 1], pt.y, c_wts[12 + c]));
            h01 = silu2p(pk2(pre[0], pre[1]));
            h23 = silu2p(pk2(pre[2], pre[3]));
            h45 = silu2p(pk2(pre[4], pre[5]));
        }

        // layer 0 modulation
        modulate2(h01, h23, h45, h2f2(v0), h2f2(v1), h2f2(v2),
                                 h2f2(v3), h2f2(v4), h2f2(v5));

        // hidden layer (scalar FFMA w/ const-bank weights), back to packed for silu
        {
            float2 a = upk(h01), b = upk(h23), c = upk(h45);
            float hh[6] = {a.x, a.y, b.x, b.y, c.x, c.y};
            float pre[6];
#pragma unroll
            for (int cc = 0; cc < 6; cc++) {
                float acc = c_wts[54 + cc];
#pragma unroll
                for (int k = 0; k < 6; k++) acc = fmaf(c_wts[18 + cc * 6 + k], hh[k], acc);
                pre[cc] = acc;
            }
            h01 = silu2p(pk2(pre[0], pre[1]));
            h23 = silu2p(pk2(pre[2], pre[3]));
            h45 = silu2p(pk2(pre[4], pre[5]));
        }

        // layer 1 modulation
        modulate2(h01, h23, h45, h2f2(v6), h2f2(v7), h2f2(v8),
                                 h2f2(v9), h2f2(v10), h2f2(v11));

        // output layer
        {
            float2 a = upk(h01), b = upk(h23), c = upk(h45);
            float hh[6] = {a.x, a.y, b.x, b.y, c.x, c.y};
#pragma unroll
            for (int j = 0; j < 3; j++) {
                float acc = c_wts[78 + j];
#pragma unroll
                for (int k = 0; k < 6; k++) acc = fmaf(c_wts[60 + j * 6 + k], hh[k], acc);
                out[3 * i + j] = acc;
            }
        }
    }
}

extern "C" void kernel_launch(void* const* d_in, const int* in_sizes, int n_in,
                              void* d_out, int out_size) {
    const float* xy    = (const float*)d_in[0];
    const float* gamma = (const float*)d_in[1];
    const float* beta  = (const float*)d_in[2];
    const float* w_in  = (const float*)d_in[3];
    const float* b_in  = (const float*)d_in[4];
    const float* w_h   = (const float*)d_in[5];
    const float* b_h   = (const float*)d_in[6];
    const float* w_out = (const float*)d_in[7];
    const float* b_out = (const float*)d_in[8];
    const float* ln_w  = (const float*)d_in[9];
    const float* ln_b  = (const float*)d_in[10];
    float* out = (float*)d_out;
    int n = in_sizes[0] / 2;

    cudaMemcpyToSymbolAsync(c_wts, w_in,  12 * sizeof(float),  0 * sizeof(float), cudaMemcpyDeviceToDevice);
    cudaMemcpyToSymbolAsync(c_wts, b_in,   6 * sizeof(float), 12 * sizeof(float), cudaMemcpyDeviceToDevice);
    cudaMemcpyToSymbolAsync(c_wts, w_h,   36 * sizeof(float), 18 * sizeof(float), cudaMemcpyDeviceToDevice);
    cudaMemcpyToSymbolAsync(c_wts, b_h,    6 * sizeof(float), 54 * sizeof(float), cudaMemcpyDeviceToDevice);
    cudaMemcpyToSymbolAsync(c_wts, w_out, 18 * sizeof(float), 60 * sizeof(float), cudaMemcpyDeviceToDevice);
    cudaMemcpyToSymbolAsync(c_wts, b_out,  3 * sizeof(float), 78 * sizeof(float), cudaMemcpyDeviceToDevice);

    prep_kernel<<<(NCELL * 12 + 255) / 256, 256>>>(gamma, beta, ln_w, ln_b);
    camfield_kernel<<<444, 256>>>((const float2*)xy, out, n);
}

// round 4
// speedup vs baseline: 1.2833x; 1.2833x over previous
#include <cuda_runtime.h>
#include <cuda_fp16.h>

#define GR 16
#define NCELL 256
typedef unsigned long long ull;

// fp16 grid: per cell 12 half2: [0..2]=A0 (gamma*ln_w-1), [3..5]=B0, [6..8]=A1, [9..11]=B1
__device__ unsigned g_gridh[NCELL * 12];
__device__ float g_wstage[81];
__constant__ float c_wts[81];   // w_in@0(12) b_in@12(6) w_h@18(36) b_h@54(6) w_out@60(18) b_out@78(3)

__global__ void prep_kernel(const float* __restrict__ gamma, const float* __restrict__ beta,
                            const float* __restrict__ lnw, const float* __restrict__ lnb,
                            const float* __restrict__ w_in, const float* __restrict__ b_in,
                            const float* __restrict__ w_h,  const float* __restrict__ b_h,
                            const float* __restrict__ w_out,const float* __restrict__ b_out) {
    int idx = blockIdx.x * blockDim.x + threadIdx.x;
    if (idx < NCELL * 12) {
        int cell = idx / 12, j = idx - cell * 12;
        int l = j / 6, jj = j - l * 6;
        int isB = jj / 3, pr = jj - isB * 3;
        float v[2];
#pragma unroll
        for (int u = 0; u < 2; u++) {
            int c = 2 * pr + u;
            float g = gamma[(l * 6 + c) * NCELL + cell];
            if (isB) v[u] = beta[(l * 6 + c) * NCELL + cell] + g * lnb[l * 6 + c];
            else     v[u] = g * lnw[l * 6 + c] - 1.0f;
        }
        __half2 h = __floats2half2_rn(v[0], v[1]);
        g_gridh[cell * 12 + j] = *reinterpret_cast<unsigned*>(&h);
    } else {
        int w = idx - NCELL * 12;
        if (w < 81) {
            float val;
            if      (w < 12) val = w_in[w];
            else if (w < 18) val = b_in[w - 12];
            else if (w < 54) val = w_h[w - 18];
            else if (w < 60) val = b_h[w - 54];
            else if (w < 78) val = w_out[w - 60];
            else             val = b_out[w - 78];
            g_wstage[w] = val;
        }
    }
}

// ---------------- packed f32x2 helpers ----------------
__device__ __forceinline__ ull pk2(float a, float b) {
    ull r; asm("mov.b64 %0, {%1,%2};" : "=l"(r) : "f"(a), "f"(b)); return r;
}
__device__ __forceinline__ float2 upk(ull r) {
    float2 o; asm("mov.b64 {%0,%1}, %2;" : "=f"(o.x), "=f"(o.y) : "l"(r)); return o;
}
#define C2(v) pk2((v), (v))
#define FMA2(d, a, b, c) asm("fma.rn.f32x2 %0,%1,%2,%3;" : "=l"(d) : "l"(a), "l"(b), "l"(c))
#define MUL2(d, a, b)    asm("mul.rn.f32x2 %0,%1,%2;"    : "=l"(d) : "l"(a), "l"(b))
#define ADD2(d, a, b)    asm("add.rn.f32x2 %0,%1,%2;"    : "=l"(d) : "l"(a), "l"(b))

// Packed silu, zero MUFU.
__device__ __forceinline__ ull silu2p(ull x) {
    float2 xv = upk(x);
    ull nax = x | 0x8000000080000000ull;      // -|x|
    ull y;  MUL2(y, nax, C2(1.4426950408889634f));
    ull fm; ADD2(fm, y, C2(12582912.0f));
    float2 fmv = upk(fm);
    int n0 = __float_as_int(fmv.x) << 23;
    int n1 = __float_as_int(fmv.y) << 23;
    ull fms; ADD2(fms, fm, C2(-12582912.0f));
    ull f;   FMA2(f, fms, C2(-1.0f), y);
    ull p;
    FMA2(p, f, C2(1.3333558e-3f), C2(9.6181291e-3f));
    FMA2(p, f, p, C2(5.5504109e-2f));
    FMA2(p, f, p, C2(2.4022651e-1f));
    FMA2(p, f, p, C2(6.9314718e-1f));
    FMA2(p, f, p, C2(1.0f));
    float2 pv = upk(p);
    ull t = pk2(__int_as_float(__float_as_int(pv.x) + n0),
                __int_as_float(__float_as_int(pv.y) + n1));
    ull d;  ADD2(d, t, C2(1.0f));
    ull r;  FMA2(r, d, C2(-8.0f / 17.0f), C2(24.0f / 17.0f));
    ull nd = d ^ 0x8000000080000000ull;
    ull u;
    FMA2(u, nd, r, C2(2.0f)); MUL2(r, r, u);
    FMA2(u, nd, r, C2(2.0f)); MUL2(r, r, u);
    ull s;  MUL2(s, t, r);
    ull m;  MUL2(m, x, s);
    float2 mv = upk(m);
    return pk2(xv.x > 0.0f ? xv.x - mv.x : mv.x,
               xv.y > 0.0f ? xv.y - mv.y : mv.y);
}

__device__ __forceinline__ __half2 hr(unsigned u) { return *reinterpret_cast<__half2*>(&u); }
__device__ __forceinline__ ull h2f2(__half2 v) { float2 f = __half22float2(v); return pk2(f.x, f.y); }

// packed layernorm + FiLM; A delta-coded: h = (1+A)*norm + B
__device__ __forceinline__ void modulate2(ull& h01, ull& h23, ull& h45,
                                          ull A01, ull A23, ull A45,
                                          ull B01, ull B23, ull B45) {
    ull sp; ADD2(sp, h01, h23); ADD2(sp, sp, h45);
    float2 sv = upk(sp);
    float nmu = (sv.x + sv.y) * (-1.0f / 6.0f);
    ull nmu2 = C2(nmu);
    ull c01, c23, c45;
    ADD2(c01, h01, nmu2); ADD2(c23, h23, nmu2); ADD2(c45, h45, nmu2);
    ull q; MUL2(q, c01, c01); FMA2(q, c23, c23, q); FMA2(q, c45, c45, q);
    float2 qv = upk(q);
    float v = fmaf(qv.x + qv.y, 1.0f / 6.0f, 1e-5f);
    float r = __int_as_float(0x5f3759df - (__float_as_int(v) >> 1));
    float hv = 0.5f * v;
    r = r * fmaf(-hv, r * r, 1.5f);
    r = r * fmaf(-hv, r * r, 1.5f);
    ull r2 = C2(r);
    ull t01, t23, t45;
    MUL2(t01, c01, r2); MUL2(t23, c23, r2); MUL2(t45, c45, r2);
    ull u01, u23, u45;
    ADD2(u01, t01, B01); ADD2(u23, t23, B23); ADD2(u45, t45, B45);
    FMA2(h01, A01, t01, u01); FMA2(h23, A23, t23, u23); FMA2(h45, A45, t45, u45);
}

#define CMB(dst, Aw, Bw, Cw, Dw) \
    dst = __hfma2(hr(Dw), W11, __hfma2(hr(Cw), W10, __hfma2(hr(Bw), W01, __hmul2(hr(Aw), W00))))

// process one point; sg = smem grid base
__device__ __forceinline__ void process_pt(const unsigned* __restrict__ sg, float px, float py,
                                           float& o0, float& o1, float& o2) {
    float fx = fminf(fmaxf(fmaf(px, 7.5f, 7.5f), 0.0f), 15.0f);
    float fy = fminf(fmaxf(fmaf(py, 7.5f, 7.5f), 0.0f), 15.0f);
    float x0f = floorf(fx), y0f = floorf(fy);
    float wx = fx - x0f, wy = fy - y0f;
    int x0 = (int)x0f, y0 = (int)y0f;
    int x1 = min(x0 + 1, GR - 1), y1 = min(y0 + 1, GR - 1);
    const uint4* p00 = (const uint4*)&sg[((y0 << 4) + x0) * 20];
    const uint4* p01 = (const uint4*)&sg[((y0 << 4) + x1) * 20];
    const uint4* p10 = (const uint4*)&sg[((y1 << 4) + x0) * 20];
    const uint4* p11 = (const uint4*)&sg[((y1 << 4) + x1) * 20];

    float w11f = wx * wy;
    __half2 W11 = __float2half2_rn(w11f);
    __half2 W01 = __float2half2_rn(wx - w11f);
    __half2 W10 = __float2half2_rn(wy - w11f);
    __half2 W00 = __float2half2_rn(1.0f - wx - wy + w11f);

    uint4 a0 = p00[0], a1 = p00[1], a2 = p00[2];
    uint4 b0 = p01[0], b1 = p01[1], b2 = p01[2];
    uint4 c0 = p10[0], c1 = p10[1], c2 = p10[2];
    uint4 d0 = p11[0], d1 = p11[1], d2 = p11[2];

    __half2 v0, v1, v2, v3, v4, v5, v6, v7, v8, v9, v10, v11;
    CMB(v0,  a0.x, b0.x, c0.x, d0.x);  CMB(v1,  a0.y, b0.y, c0.y, d0.y);
    CMB(v2,  a0.z, b0.z, c0.z, d0.z);  CMB(v3,  a0.w, b0.w, c0.w, d0.w);
    CMB(v4,  a1.x, b1.x, c1.x, d1.x);  CMB(v5,  a1.y, b1.y, c1.y, d1.y);
    CMB(v6,  a1.z, b1.z, c1.z, d1.z);  CMB(v7,  a1.w, b1.w, c1.w, d1.w);
    CMB(v8,  a2.x, b2.x, c2.x, d2.x);  CMB(v9,  a2.y, b2.y, c2.y, d2.y);
    CMB(v10, a2.z, b2.z, c2.z, d2.z);  CMB(v11, a2.w, b2.w, c2.w, d2.w);

    ull h01, h23, h45;
    {
        float pre[6];
#pragma unroll
        for (int c = 0; c < 6; c++)
            pre[c] = fmaf(c_wts[2 * c], px, fmaf(c_wts[2 * c + 1], py, c_wts[12 + c]));
        h01 = silu2p(pk2(pre[0], pre[1]));
        h23 = silu2p(pk2(pre[2], pre[3]));
        h45 = silu2p(pk2(pre[4], pre[5]));
    }

    modulate2(h01, h23, h45, h2f2(v0), h2f2(v1), h2f2(v2),
                             h2f2(v3), h2f2(v4), h2f2(v5));

    {
        float2 a = upk(h01), b = upk(h23), c = upk(h45);
        float hh[6] = {a.x, a.y, b.x, b.y, c.x, c.y};
        float pre[6];
#pragma unroll
        for (int cc = 0; cc < 6; cc++) {
            float acc = c_wts[54 + cc];
#pragma unroll
            for (int k = 0; k < 6; k++) acc = fmaf(c_wts[18 + cc * 6 + k], hh[k], acc);
            pre[cc] = acc;
        }
        h01 = silu2p(pk2(pre[0], pre[1]));
        h23 = silu2p(pk2(pre[2], pre[3]));
        h45 = silu2p(pk2(pre[4], pre[5]));
    }

    modulate2(h01, h23, h45, h2f2(v6), h2f2(v7), h2f2(v8),
                             h2f2(v9), h2f2(v10), h2f2(v11));

    {
        float2 a = upk(h01), b = upk(h23), c = upk(h45);
        float hh[6] = {a.x, a.y, b.x, b.y, c.x, c.y};
        float acc[3];
#pragma unroll
        for (int j = 0; j < 3; j++) {
            float s = c_wts[78 + j];
#pragma unroll
            for (int k = 0; k < 6; k++) s = fmaf(c_wts[60 + j * 6 + k], hh[k], s);
            acc[j] = s;
        }
        o0 = acc[0]; o1 = acc[1]; o2 = acc[2];
    }
}

// ---------------- main kernel: 2 points/thread for ILP ----------------
__global__ __launch_bounds__(256, 3)
void camfield_kernel(const float4* __restrict__ xy2, float2* __restrict__ out2, int npair) {
    __shared__ __align__(16) unsigned sg[NCELL * 20];   // stride 20 words (5x16B chunks)
    for (int i = threadIdx.x; i < NCELL * 12; i += blockDim.x)
        sg[(i / 12) * 20 + (i % 12)] = g_gridh[i];
    __syncthreads();

    const int stride = gridDim.x * blockDim.x;
#pragma unroll 1
    for (int i = blockIdx.x * blockDim.x + threadIdx.x; i < npair; i += stride) {
        float4 pp = xy2[i];                 // points 2i, 2i+1
        float aa0, aa1, aa2, bb0, bb1, bb2;
        process_pt(sg, pp.x, pp.y, aa0, aa1, aa2);
        process_pt(sg, pp.z, pp.w, bb0, bb1, bb2);
        out2[3 * i + 0] = make_float2(aa0, aa1);
        out2[3 * i + 1] = make_float2(aa2, bb0);
        out2[3 * i + 2] = make_float2(bb1, bb2);
    }
}

extern "C" void kernel_launch(void* const* d_in, const int* in_sizes, int n_in,
                              void* d_out, int out_size) {
    const float* xy    = (const float*)d_in[0];
    const float* gamma = (const float*)d_in[1];
    const float* beta  = (const float*)d_in[2];
    const float* w_in  = (const float*)d_in[3];
    const float* b_in  = (const float*)d_in[4];
    const float* w_h   = (const float*)d_in[5];
    const float* b_h   = (const float*)d_in[6];
    const float* w_out = (const float*)d_in[7];
    const float* b_out = (const float*)d_in[8];
    const float* ln_w  = (const float*)d_in[9];
    const float* ln_b  = (const float*)d_in[10];
    float* out = (float*)d_out;
    int n = in_sizes[0] / 2;
    int npair = n / 2;                      // N_POINTS is even

    prep_kernel<<<13, 256>>>(gamma, beta, ln_w, ln_b,
                             w_in, b_in, w_h, b_h, w_out, b_out);

    void* stage_ptr = nullptr;
    cudaGetSymbolAddress(&stage_ptr, g_wstage);
    cudaMemcpyToSymbolAsync(c_wts, stage_ptr, 81 * sizeof(float), 0,
                            cudaMemcpyDeviceToDevice);

    camfield_kernel<<<444, 256>>>((const float4*)xy, (float2*)out, npair);
}

// round 6
// speedup vs baseline: 1.5570x; 1.2133x over previous
#include <cuda_runtime.h>
#include <cuda_fp16.h>

#define GR 16
#define NCELL 256
typedef unsigned long long ull;

// fp16 grid: per cell 12 half2: [0..2]=A0 (gamma*ln_w-1), [3..5]=B0, [6..8]=A1, [9..11]=B1
__device__ unsigned g_gridh[NCELL * 12];
__device__ float g_wstage[81];
__constant__ float c_wts[81];   // w_in@0(12) b_in@12(6) w_h@18(36) b_h@54(6) w_out@60(18) b_out@78(3)

__global__ void prep_kernel(const float* __restrict__ gamma, const float* __restrict__ beta,
                            const float* __restrict__ lnw, const float* __restrict__ lnb,
                            const float* __restrict__ w_in, const float* __restrict__ b_in,
                            const float* __restrict__ w_h,  const float* __restrict__ b_h,
                            const float* __restrict__ w_out,const float* __restrict__ b_out) {
    int idx = blockIdx.x * blockDim.x + threadIdx.x;
    if (idx < NCELL * 12) {
        int cell = idx / 12, j = idx - cell * 12;
        int l = j / 6, jj = j - l * 6;
        int isB = jj / 3, pr = jj - isB * 3;
        float v[2];
#pragma unroll
        for (int u = 0; u < 2; u++) {
            int c = 2 * pr + u;
            float g = gamma[(l * 6 + c) * NCELL + cell];
            if (isB) v[u] = beta[(l * 6 + c) * NCELL + cell] + g * lnb[l * 6 + c];
            else     v[u] = g * lnw[l * 6 + c] - 1.0f;
        }
        __half2 h = __floats2half2_rn(v[0], v[1]);
        g_gridh[cell * 12 + j] = *reinterpret_cast<unsigned*>(&h);
    } else {
        int w = idx - NCELL * 12;
        if (w < 81) {
            float val;
            if      (w < 12) val = w_in[w];
            else if (w < 18) val = b_in[w - 12];
            else if (w < 54) val = w_h[w - 18];
            else if (w < 60) val = b_h[w - 54];
            else if (w < 78) val = w_out[w - 60];
            else             val = b_out[w - 78];
            g_wstage[w] = val;
        }
    }
}

// ---------------- packed f32x2 helpers (kept for modulate) ----------------
__device__ __forceinline__ ull pk2(float a, float b) {
    ull r; asm("mov.b64 %0, {%1,%2};" : "=l"(r) : "f"(a), "f"(b)); return r;
}
__device__ __forceinline__ float2 upk(ull r) {
    float2 o; asm("mov.b64 {%0,%1}, %2;" : "=f"(o.x), "=f"(o.y) : "l"(r)); return o;
}
#define C2(v) pk2((v), (v))
#define FMA2(d, a, b, c) asm("fma.rn.f32x2 %0,%1,%2,%3;" : "=l"(d) : "l"(a), "l"(b), "l"(c))
#define MUL2(d, a, b)    asm("mul.rn.f32x2 %0,%1,%2;"    : "=l"(d) : "l"(a), "l"(b))
#define ADD2(d, a, b)    asm("add.rn.f32x2 %0,%1,%2;"    : "=l"(d) : "l"(a), "l"(b))

// ---------------- MUFU-based math ----------------
__device__ __forceinline__ float mufu_ex2(float x) {
    float r; asm("ex2.approx.ftz.f32 %0, %1;" : "=f"(r) : "f"(x)); return r;
}
__device__ __forceinline__ float mufu_rcp(float x) {
    float r; asm("rcp.approx.ftz.f32 %0, %1;" : "=f"(r) : "f"(x)); return r;
}
__device__ __forceinline__ float mufu_rsqrt(float x) {
    float r; asm("rsqrt.approx.ftz.f32 %0, %1;" : "=f"(r) : "f"(x)); return r;
}

// silu(x) = x / (1 + e^{-x}); e^{-x} = 2^{-x*log2e}. ex2->inf / ->0 tails give
// exactly the right limits through rcp. 3 fma-pipe ops + 2 MUFU.
__device__ __forceinline__ float silu1(float x) {
    float t = mufu_ex2(x * -1.4426950408889634f);
    return x * mufu_rcp(1.0f + t);
}

__device__ __forceinline__ __half2 hr(unsigned u) { return *reinterpret_cast<__half2*>(&u); }
__device__ __forceinline__ ull h2f2(__half2 v) { float2 f = __half22float2(v); return pk2(f.x, f.y); }

// packed layernorm + FiLM; A delta-coded: h = (1+A)*norm + B
__device__ __forceinline__ void modulate2(ull& h01, ull& h23, ull& h45,
                                          ull A01, ull A23, ull A45,
                                          ull B01, ull B23, ull B45) {
    ull sp; ADD2(sp, h01, h23); ADD2(sp, sp, h45);
    float2 sv = upk(sp);
    float nmu = (sv.x + sv.y) * (-1.0f / 6.0f);
    ull nmu2 = C2(nmu);
    ull c01, c23, c45;
    ADD2(c01, h01, nmu2); ADD2(c23, h23, nmu2); ADD2(c45, h45, nmu2);
    ull q; MUL2(q, c01, c01); FMA2(q, c23, c23, q); FMA2(q, c45, c45, q);
    float2 qv = upk(q);
    float r = mufu_rsqrt(fmaf(qv.x + qv.y, 1.0f / 6.0f, 1e-5f));
    ull r2 = C2(r);
    ull t01, t23, t45;
    MUL2(t01, c01, r2); MUL2(t23, c23, r2); MUL2(t45, c45, r2);
    ull u01, u23, u45;
    ADD2(u01, t01, B01); ADD2(u23, t23, B23); ADD2(u45, t45, B45);
    FMA2(h01, A01, t01, u01); FMA2(h23, A23, t23, u23); FMA2(h45, A45, t45, u45);
}

#define CMB(dst, Aw, Bw, Cw, Dw) \
    dst = __hfma2(hr(Dw), W11, __hfma2(hr(Cw), W10, __hfma2(hr(Bw), W01, __hmul2(hr(Aw), W00))))

// process one point; sg = smem grid base
__device__ __forceinline__ void process_pt(const unsigned* __restrict__ sg, float px, float py,
                                           float& o0, float& o1, float& o2) {
    float fx = fminf(fmaxf(fmaf(px, 7.5f, 7.5f), 0.0f), 15.0f);
    float fy = fminf(fmaxf(fmaf(py, 7.5f, 7.5f), 0.0f), 15.0f);
    float x0f = floorf(fx), y0f = floorf(fy);
    float wx = fx - x0f, wy = fy - y0f;
    int x0 = (int)x0f, y0 = (int)y0f;
    int x1 = min(x0 + 1, GR - 1), y1 = min(y0 + 1, GR - 1);
    const uint4* p00 = (const uint4*)&sg[((y0 << 4) + x0) * 20];
    const uint4* p01 = (const uint4*)&sg[((y0 << 4) + x1) * 20];
    const uint4* p10 = (const uint4*)&sg[((y1 << 4) + x0) * 20];
    const uint4* p11 = (const uint4*)&sg[((y1 << 4) + x1) * 20];

    float w11f = wx * wy;
    __half2 W11 = __float2half2_rn(w11f);
    __half2 W01 = __float2half2_rn(wx - w11f);
    __half2 W10 = __float2half2_rn(wy - w11f);
    __half2 W00 = __float2half2_rn(1.0f - wx - wy + w11f);

    uint4 a0 = p00[0], a1 = p00[1], a2 = p00[2];
    uint4 b0 = p01[0], b1 = p01[1], b2 = p01[2];
    uint4 c0 = p10[0], c1 = p10[1], c2 = p10[2];
    uint4 d0 = p11[0], d1 = p11[1], d2 = p11[2];

    __half2 v0, v1, v2, v3, v4, v5, v6, v7, v8, v9, v10, v11;
    CMB(v0,  a0.x, b0.x, c0.x, d0.x);  CMB(v1,  a0.y, b0.y, c0.y, d0.y);
    CMB(v2,  a0.z, b0.z, c0.z, d0.z);  CMB(v3,  a0.w, b0.w, c0.w, d0.w);
    CMB(v4,  a1.x, b1.x, c1.x, d1.x);  CMB(v5,  a1.y, b1.y, c1.y, d1.y);
    CMB(v6,  a1.z, b1.z, c1.z, d1.z);  CMB(v7,  a1.w, b1.w, c1.w, d1.w);
    CMB(v8,  a2.x, b2.x, c2.x, d2.x);  CMB(v9,  a2.y, b2.y, c2.y, d2.y);
    CMB(v10, a2.z, b2.z, c2.z, d2.z);  CMB(v11, a2.w, b2.w, c2.w, d2.w);

    // input layer: silu(xy @ w_in^T + b_in)
    float s0 = silu1(fmaf(c_wts[0],  px, fmaf(c_wts[1],  py, c_wts[12])));
    float s1 = silu1(fmaf(c_wts[2],  px, fmaf(c_wts[3],  py, c_wts[13])));
    float s2 = silu1(fmaf(c_wts[4],  px, fmaf(c_wts[5],  py, c_wts[14])));
    float s3 = silu1(fmaf(c_wts[6],  px, fmaf(c_wts[7],  py, c_wts[15])));
    float s4 = silu1(fmaf(c_wts[8],  px, fmaf(c_wts[9],  py, c_wts[16])));
    float s5 = silu1(fmaf(c_wts[10], px, fmaf(c_wts[11], py, c_wts[17])));
    ull h01 = pk2(s0, s1), h23 = pk2(s2, s3), h45 = pk2(s4, s5);

    // layer 0 modulation
    modulate2(h01, h23, h45, h2f2(v0), h2f2(v1), h2f2(v2),
                             h2f2(v3), h2f2(v4), h2f2(v5));

    // hidden layer
    {
        float2 a = upk(h01), b = upk(h23), c = upk(h45);
        float hh[6] = {a.x, a.y, b.x, b.y, c.x, c.y};
        float pre[6];
#pragma unroll
        for (int cc = 0; cc < 6; cc++) {
            float acc = c_wts[54 + cc];
#pragma unroll
            for (int k = 0; k < 6; k++) acc = fmaf(c_wts[18 + cc * 6 + k], hh[k], acc);
            pre[cc] = acc;
        }
        h01 = pk2(silu1(pre[0]), silu1(pre[1]));
        h23 = pk2(silu1(pre[2]), silu1(pre[3]));
        h45 = pk2(silu1(pre[4]), silu1(pre[5]));
    }

    // layer 1 modulation
    modulate2(h01, h23, h45, h2f2(v6), h2f2(v7), h2f2(v8),
                             h2f2(v9), h2f2(v10), h2f2(v11));

    // output layer
    {
        float2 a = upk(h01), b = upk(h23), c = upk(h45);
        float hh[6] = {a.x, a.y, b.x, b.y, c.x, c.y};
        float acc[3];
#pragma unroll
        for (int j = 0; j < 3; j++) {
            float s = c_wts[78 + j];
#pragma unroll
            for (int k = 0; k < 6; k++) s = fmaf(c_wts[60 + j * 6 + k], hh[k], s);
            acc[j] = s;
        }
        o0 = acc[0]; o1 = acc[1]; o2 = acc[2];
    }
}

// ---------------- main kernel: 2 points/thread ----------------
__global__ __launch_bounds__(256, 3)
void camfield_kernel(const float4* __restrict__ xy2, float2* __restrict__ out2, int npair) {
    __shared__ __align__(16) unsigned sg[NCELL * 20];   // stride 20 words (5x16B chunks)
    for (int i = threadIdx.x; i < NCELL * 12; i += blockDim.x)
        sg[(i / 12) * 20 + (i % 12)] = g_gridh[i];
    __syncthreads();

    const int stride = gridDim.x * blockDim.x;
#pragma unroll 1
    for (int i = blockIdx.x * blockDim.x + threadIdx.x; i < npair; i += stride) {
        float4 pp = xy2[i];                 // points 2i, 2i+1
        float aa0, aa1, aa2, bb0, bb1, bb2;
        process_pt(sg, pp.x, pp.y, aa0, aa1, aa2);
        process_pt(sg, pp.z, pp.w, bb0, bb1, bb2);
        out2[3 * i + 0] = make_float2(aa0, aa1);
        out2[3 * i + 1] = make_float2(aa2, bb0);
        out2[3 * i + 2] = make_float2(bb1, bb2);
    }
}

extern "C" void kernel_launch(void* const* d_in, const int* in_sizes, int n_in,
                              void* d_out, int out_size) {
    const float* xy    = (const float*)d_in[0];
    const float* gamma = (const float*)d_in[1];
    const float* beta  = (const float*)d_in[2];
    const float* w_in  = (const float*)d_in[3];
    const float* b_in  = (const float*)d_in[4];
    const float* w_h   = (const float*)d_in[5];
    const float* b_h   = (const float*)d_in[6];
    const float* w_out = (const float*)d_in[7];
    const float* b_out = (const float*)d_in[8];
    const float* ln_w  = (const float*)d_in[9];
    const float* ln_b  = (const float*)d_in[10];
    float* out = (float*)d_out;
    int n = in_sizes[0] / 2;
    int npair = n / 2;                      // N_POINTS is even

    prep_kernel<<<13, 256>>>(gamma, beta, ln_w, ln_b,
                             w_in, b_in, w_h, b_h, w_out, b_out);

    void* stage_ptr = nullptr;
    cudaGetSymbolAddress(&stage_ptr, g_wstage);
    cudaMemcpyToSymbolAsync(c_wts, stage_ptr, 81 * sizeof(float), 0,
                            cudaMemcpyDeviceToDevice);

    camfield_kernel<<<444, 256>>>((const float4*)xy, (float2*)out, npair);
}

// round 7
// speedup vs baseline: 1.7145x; 1.1012x over previous
#include <cuda_runtime.h>
#include <cuda_fp16.h>

#define GR 16
#define NCELL 256
typedef unsigned long long ull;

// fp16 grid, per cell 12 half2 words = 3 uint4 chunks:
// chunk0 = A0(3 half2) + B0[0]; packed order: [0..2]=A0, [3..5]=B0, [6..8]=A1, [9..11]=B1
__device__ uint4 g_gridq[NCELL * 3];
__device__ float g_wstage[81];
__constant__ float c_wts[81];   // w_in@0(12) b_in@12(6) w_h@18(36) b_h@54(6) w_out@60(18) b_out@78(3)

__global__ void prep_kernel(const float* __restrict__ gamma, const float* __restrict__ beta,
                            const float* __restrict__ lnw, const float* __restrict__ lnb,
                            const float* __restrict__ w_in, const float* __restrict__ b_in,
                            const float* __restrict__ w_h,  const float* __restrict__ b_h,
                            const float* __restrict__ w_out,const float* __restrict__ b_out) {
    int idx = blockIdx.x * blockDim.x + threadIdx.x;
    if (idx < NCELL * 12) {
        int cell = idx / 12, j = idx - cell * 12;
        int l = j / 6, jj = j - l * 6;
        int isB = jj / 3, pr = jj - isB * 3;
        float v[2];
#pragma unroll
        for (int u = 0; u < 2; u++) {
            int c = 2 * pr + u;
            float g = gamma[(l * 6 + c) * NCELL + cell];
            if (isB) v[u] = beta[(l * 6 + c) * NCELL + cell] + g * lnb[l * 6 + c];
            else     v[u] = g * lnw[l * 6 + c] - 1.0f;
        }
        __half2 h = __floats2half2_rn(v[0], v[1]);
        reinterpret_cast<unsigned*>(g_gridq)[cell * 12 + j] = *reinterpret_cast<unsigned*>(&h);
    } else {
        int w = idx - NCELL * 12;
        if (w < 81) {
            float val;
            if      (w < 12) val = w_in[w];
            else if (w < 18) val = b_in[w - 12];
            else if (w < 54) val = w_h[w - 18];
            else if (w < 60) val = b_h[w - 54];
            else if (w < 78) val = w_out[w - 60];
            else             val = b_out[w - 78];
            g_wstage[w] = val;
        }
    }
}

// ---------------- packed f32x2 helpers ----------------
__device__ __forceinline__ ull pk2(float a, float b) {
    ull r; asm("mov.b64 %0, {%1,%2};" : "=l"(r) : "f"(a), "f"(b)); return r;
}
__device__ __forceinline__ float2 upk(ull r) {
    float2 o; asm("mov.b64 {%0,%1}, %2;" : "=f"(o.x), "=f"(o.y) : "l"(r)); return o;
}
#define C2(v) pk2((v), (v))
#define FMA2(d, a, b, c) asm("fma.rn.f32x2 %0,%1,%2,%3;" : "=l"(d) : "l"(a), "l"(b), "l"(c))
#define MUL2(d, a, b)    asm("mul.rn.f32x2 %0,%1,%2;"    : "=l"(d) : "l"(a), "l"(b))
#define ADD2(d, a, b)    asm("add.rn.f32x2 %0,%1,%2;"    : "=l"(d) : "l"(a), "l"(b))

// ---------------- MUFU math ----------------
__device__ __forceinline__ float mufu_ex2(float x) {
    float r; asm("ex2.approx.ftz.f32 %0, %1;" : "=f"(r) : "f"(x)); return r;
}
__device__ __forceinline__ float mufu_rcp(float x) {
    float r; asm("rcp.approx.ftz.f32 %0, %1;" : "=f"(r) : "f"(x)); return r;
}
__device__ __forceinline__ float mufu_rsqrt(float x) {
    float r; asm("rsqrt.approx.ftz.f32 %0, %1;" : "=f"(r) : "f"(x)); return r;
}

// silu(x) = x / (1 + 2^{-x*log2e}); tails exact through rcp.
__device__ __forceinline__ float silu1(float x) {
    float t = mufu_ex2(x * -1.4426950408889634f);
    return x * mufu_rcp(1.0f + t);
}

__device__ __forceinline__ __half2 hr(unsigned u) { return *reinterpret_cast<__half2*>(&u); }
__device__ __forceinline__ ull h2f2(__half2 v) { float2 f = __half22float2(v); return pk2(f.x, f.y); }

// packed layernorm + FiLM; A delta-coded: h = (1+A)*norm + B
__device__ __forceinline__ void modulate2(ull& h01, ull& h23, ull& h45,
                                          ull A01, ull A23, ull A45,
                                          ull B01, ull B23, ull B45) {
    ull sp; ADD2(sp, h01, h23); ADD2(sp, sp, h45);
    float2 sv = upk(sp);
    float nmu = (sv.x + sv.y) * (-1.0f / 6.0f);
    ull nmu2 = C2(nmu);
    ull c01, c23, c45;
    ADD2(c01, h01, nmu2); ADD2(c23, h23, nmu2); ADD2(c45, h45, nmu2);
    ull q; MUL2(q, c01, c01); FMA2(q, c23, c23, q); FMA2(q, c45, c45, q);
    float2 qv = upk(q);
    float r = mufu_rsqrt(fmaf(qv.x + qv.y, 1.0f / 6.0f, 1e-5f));
    ull r2 = C2(r);
    ull t01, t23, t45;
    MUL2(t01, c01, r2); MUL2(t23, c23, r2); MUL2(t45, c45, r2);
    ull u01, u23, u45;
    ADD2(u01, t01, B01); ADD2(u23, t23, B23); ADD2(u45, t45, B45);
    FMA2(h01, A01, t01, u01); FMA2(h23, A23, t23, u23); FMA2(h45, A45, t45, u45);
}

#define CMB(dst, Aw, Bw, Cw, Dw) \
    dst = __hfma2(hr(Dw), W11, __hfma2(hr(Cw), W10, __hfma2(hr(Bw), W01, __hmul2(hr(Aw), W00))))

// process one point; sgq = replicated smem grid (uint4 view), lr = lane & 7
__device__ __forceinline__ void process_pt(const uint4* __restrict__ sgq, int lr,
                                           float px, float py,
                                           float& o0, float& o1, float& o2) {
    float fx = fminf(fmaxf(fmaf(px, 7.5f, 7.5f), 0.0f), 15.0f);
    float fy = fminf(fmaxf(fmaf(py, 7.5f, 7.5f), 0.0f), 15.0f);
    float x0f = floorf(fx), y0f = floorf(fy);
    float wx = fx - x0f, wy = fy - y0f;
    int x0 = (int)x0f, y0 = (int)y0f;
    int x1 = min(x0 + 1, GR - 1), y1 = min(y0 + 1, GR - 1);
    // replicated layout: chunk (cell, j) occupies 128B block; lane reads copy lr.
    int i00 = ((y0 << 4) + x0) * 24 + lr;
    int i01 = ((y0 << 4) + x1) * 24 + lr;
    int i10 = ((y1 << 4) + x0) * 24 + lr;
    int i11 = ((y1 << 4) + x1) * 24 + lr;

    float w11f = wx * wy;
    __half2 W11 = __float2half2_rn(w11f);
    __half2 W01 = __float2half2_rn(wx - w11f);
    __half2 W10 = __float2half2_rn(wy - w11f);
    __half2 W00 = __float2half2_rn(1.0f - wx - wy + w11f);

    uint4 a0 = sgq[i00], a1 = sgq[i00 + 8], a2 = sgq[i00 + 16];
    uint4 b0 = sgq[i01], b1 = sgq[i01 + 8], b2 = sgq[i01 + 16];
    uint4 c0 = sgq[i10], c1 = sgq[i10 + 8], c2 = sgq[i10 + 16];
    uint4 d0 = sgq[i11], d1 = sgq[i11 + 8], d2 = sgq[i11 + 16];

    __half2 v0, v1, v2, v3, v4, v5, v6, v7, v8, v9, v10, v11;
    CMB(v0,  a0.x, b0.x, c0.x, d0.x);  CMB(v1,  a0.y, b0.y, c0.y, d0.y);
    CMB(v2,  a0.z, b0.z, c0.z, d0.z);  CMB(v3,  a0.w, b0.w, c0.w, d0.w);
    CMB(v4,  a1.x, b1.x, c1.x, d1.x);  CMB(v5,  a1.y, b1.y, c1.y, d1.y);
    CMB(v6,  a1.z, b1.z, c1.z, d1.z);  CMB(v7,  a1.w, b1.w, c1.w, d1.w);
    CMB(v8,  a2.x, b2.x, c2.x, d2.x);  CMB(v9,  a2.y, b2.y, c2.y, d2.y);
    CMB(v10, a2.z, b2.z, c2.z, d2.z);  CMB(v11, a2.w, b2.w, c2.w, d2.w);

    // input layer
    float s0 = silu1(fmaf(c_wts[0],  px, fmaf(c_wts[1],  py, c_wts[12])));
    float s1 = silu1(fmaf(c_wts[2],  px, fmaf(c_wts[3],  py, c_wts[13])));
    float s2 = silu1(fmaf(c_wts[4],  px, fmaf(c_wts[5],  py, c_wts[14])));
    float s3 = silu1(fmaf(c_wts[6],  px, fmaf(c_wts[7],  py, c_wts[15])));
    float s4 = silu1(fmaf(c_wts[8],  px, fmaf(c_wts[9],  py, c_wts[16])));
    float s5 = silu1(fmaf(c_wts[10], px, fmaf(c_wts[11], py, c_wts[17])));
    ull h01 = pk2(s0, s1), h23 = pk2(s2, s3), h45 = pk2(s4, s5);

    modulate2(h01, h23, h45, h2f2(v0), h2f2(v1), h2f2(v2),
                             h2f2(v3), h2f2(v4), h2f2(v5));

    {
        float2 a = upk(h01), b = upk(h23), c = upk(h45);
        float hh[6] = {a.x, a.y, b.x, b.y, c.x, c.y};
        float pre[6];
#pragma unroll
        for (int cc = 0; cc < 6; cc++) {
            float acc = c_wts[54 + cc];
#pragma unroll
            for (int k = 0; k < 6; k++) acc = fmaf(c_wts[18 + cc * 6 + k], hh[k], acc);
            pre[cc] = acc;
        }
        h01 = pk2(silu1(pre[0]), silu1(pre[1]));
        h23 = pk2(silu1(pre[2]), silu1(pre[3]));
        h45 = pk2(silu1(pre[4]), silu1(pre[5]));
    }

    modulate2(h01, h23, h45, h2f2(v6), h2f2(v7), h2f2(v8),
                             h2f2(v9), h2f2(v10), h2f2(v11));

    {
        float2 a = upk(h01), b = upk(h23), c = upk(h45);
        float hh[6] = {a.x, a.y, b.x, b.y, c.x, c.y};
        float acc[3];
#pragma unroll
        for (int j = 0; j < 3; j++) {
            float s = c_wts[78 + j];
#pragma unroll
            for (int k = 0; k < 6; k++) s = fmaf(c_wts[60 + j * 6 + k], hh[k], s);
            acc[j] = s;
        }
        o0 = acc[0]; o1 = acc[1]; o2 = acc[2];
    }
}

// ---------------- main kernel: 2 pts/thread, 8x replicated conflict-free smem ----------------
__global__ __launch_bounds__(256, 2)
void camfield_kernel(const float4* __restrict__ xy2, float2* __restrict__ out2, int npair) {
    extern __shared__ __align__(16) uint4 sgq[];   // 768 chunks x 8 copies = 96 KB
    // fill: consecutive threads write consecutive 16B copies -> conflict-free STS.128
    for (int t = threadIdx.x; t < NCELL * 3 * 8; t += blockDim.x)
        sgq[t] = g_gridq[t >> 3];
    __syncthreads();

    const int lr = threadIdx.x & 7;
    const int stride = gridDim.x * blockDim.x;
#pragma unroll 1
    for (int i = blockIdx.x * blockDim.x + threadIdx.x; i < npair; i += stride) {
        float4 pp = xy2[i];                 // points 2i, 2i+1
        float aa0, aa1, aa2, bb0, bb1, bb2;
        process_pt(sgq, lr, pp.x, pp.y, aa0, aa1, aa2);
        process_pt(sgq, lr, pp.z, pp.w, bb0, bb1, bb2);
        out2[3 * i + 0] = make_float2(aa0, aa1);
        out2[3 * i + 1] = make_float2(aa2, bb0);
        out2[3 * i + 2] = make_float2(bb1, bb2);
    }
}

extern "C" void kernel_launch(void* const* d_in, const int* in_sizes, int n_in,
                              void* d_out, int out_size) {
    const float* xy    = (const float*)d_in[0];
    const float* gamma = (const float*)d_in[1];
    const float* beta  = (const float*)d_in[2];
    const float* w_in  = (const float*)d_in[3];
    const float* b_in  = (const float*)d_in[4];
    const float* w_h   = (const float*)d_in[5];
    const float* b_h   = (const float*)d_in[6];
    const float* w_out = (const float*)d_in[7];
    const float* b_out = (const float*)d_in[8];
    const float* ln_w  = (const float*)d_in[9];
    const float* ln_b  = (const float*)d_in[10];
    float* out = (float*)d_out;
    int n = in_sizes[0] / 2;
    int npair = n / 2;                      // N_POINTS is even

    prep_kernel<<<13, 256>>>(gamma, beta, ln_w, ln_b,
                             w_in, b_in, w_h, b_h, w_out, b_out);

    void* stage_ptr = nullptr;
    cudaGetSymbolAddress(&stage_ptr, g_wstage);
    cudaMemcpyToSymbolAsync(c_wts, stage_ptr, 81 * sizeof(float), 0,
                            cudaMemcpyDeviceToDevice);

    const int smem_bytes = NCELL * 3 * 8 * 16;   // 98304
    cudaFuncSetAttribute(camfield_kernel,
                         cudaFuncAttributeMaxDynamicSharedMemorySize, smem_bytes);
    camfield_kernel<<<296, 256, smem_bytes>>>((const float4*)xy, (float2*)out, npair);
}